// round 1
// baseline (speedup 1.0000x reference)
#include <cuda_runtime.h>
#include <math.h>

#define NEPS 1e-8f
#define MEPS 1e-6f
#define BTOL 1e-6f
#define MAXV 24
#define RED_MAX 16384
#define TPB 256

__device__ float g_partials[RED_MAX];

// Corner order matches reference: x4=[.5,-.5,-.5,.5]*w, y4=[-.5,-.5,.5,.5]*h
__device__ __forceinline__ void box_corners(float cx, float cy, float w, float h,
                                            float c, float s,
                                            float* X, float* Y) {
    float hw = 0.5f * w, hh = 0.5f * h;
    float xs0 = hw, xs1 = -hw, xs2 = -hw, xs3 = hw;
    float ys0 = -hh, ys1 = -hh, ys2 = hh, ys3 = hh;
    X[0] = xs0 * c - ys0 * s + cx;  Y[0] = xs0 * s + ys0 * c + cy;
    X[1] = xs1 * c - ys1 * s + cx;  Y[1] = xs1 * s + ys1 * c + cy;
    X[2] = xs2 * c - ys2 * s + cx;  Y[2] = xs2 * s + ys2 * c + cy;
    X[3] = xs3 * c - ys3 * s + cx;  Y[3] = xs3 * s + ys3 * c + cy;
}

__device__ __forceinline__ float compute_loss(const float* __restrict__ pred,
                                              const float* __restrict__ target,
                                              const float* __restrict__ weight,
                                              int i) {
    const float* P = pred + (size_t)i * 5;
    const float* T = target + (size_t)i * 5;
    float p_cx = P[0], p_cy = P[1], p_w = P[2], p_h = P[3], p_a = P[4];
    float t_cx = T[0], t_cy = T[1], t_w = T[2], t_h = T[3], t_a = T[4];

    float c1, s1, c2, s2;
    sincosf(p_a, &s1, &c1);
    sincosf(t_a, &s2, &c2);

    float X1[4], Y1[4], X2[4], Y2[4];
    box_corners(p_cx, p_cy, p_w, p_h, c1, s1, X1, Y1);
    box_corners(t_cx, t_cy, t_w, t_h, c2, s2, X2, Y2);

    // Collect valid vertices in the reference's concatenation order:
    // corners1 (in box2), corners2 (in box1), intersections (k1-major).
    float vx[MAXV], vy[MAXV];
    int m = 0;

    // corners1 in box2:  a=C2[0], b=C2[1], d=C2[3]
    {
        float abx = X2[1] - X2[0], aby = Y2[1] - Y2[0];
        float adx = X2[3] - X2[0], ady = Y2[3] - Y2[0];
        float ab2 = abx * abx + aby * aby;
        float ad2 = adx * adx + ady * ady;
        #pragma unroll
        for (int k = 0; k < 4; k++) {
            float amx = X1[k] - X2[0], amy = Y1[k] - Y2[0];
            float pab = (abx * amx + aby * amy) / ab2;
            float pad = (adx * amx + ady * amy) / ad2;
            if (pab > -BTOL && pab < 1.0f + BTOL && pad > -BTOL && pad < 1.0f + BTOL) {
                vx[m] = X1[k]; vy[m] = Y1[k]; m++;
            }
        }
    }
    // corners2 in box1
    {
        float abx = X1[1] - X1[0], aby = Y1[1] - Y1[0];
        float adx = X1[3] - X1[0], ady = Y1[3] - Y1[0];
        float ab2 = abx * abx + aby * aby;
        float ad2 = adx * adx + ady * ady;
        #pragma unroll
        for (int k = 0; k < 4; k++) {
            float amx = X2[k] - X1[0], amy = Y2[k] - Y1[0];
            float pab = (abx * amx + aby * amy) / ab2;
            float pad = (adx * amx + ady * amy) / ad2;
            if (pab > -BTOL && pab < 1.0f + BTOL && pad > -BTOL && pad < 1.0f + BTOL) {
                vx[m] = X2[k]; vy[m] = Y2[k]; m++;
            }
        }
    }
    // segment intersections, k1 (box1 edge) major, k2 minor — matches reshape order
    #pragma unroll
    for (int k1 = 0; k1 < 4; k1++) {
        float x1 = X1[k1], y1 = Y1[k1];
        float x2 = X1[(k1 + 1) & 3], y2 = Y1[(k1 + 1) & 3];
        float ex = x2 - x1, ey = y2 - y1;
        #pragma unroll
        for (int k2 = 0; k2 < 4; k2++) {
            float x3 = X2[k2], y3 = Y2[k2];
            float x4 = X2[(k2 + 1) & 3], y4 = Y2[(k2 + 1) & 3];
            float fx = x4 - x3, fy = y4 - y3;
            float num   = fy * ex - fx * ey;
            float den_t = fx * (y1 - y3) - fy * (x1 - x3);
            float t = den_t / (num + NEPS);
            float den_u = ex * (y1 - y3) - ey * (x1 - x3);
            float u = -den_u / (num + NEPS);
            bool ok = (num != 0.0f) &&
                      (t > 0.0f) && (t < 1.0f) &&
                      (u > 0.0f) && (u < 1.0f);
            if (ok) {
                vx[m] = x1 + t * ex;
                vy[m] = y1 + t * ey;
                m++;
            }
        }
    }

    // center, centered coords, angles, stable sort, shoelace
    float inter_area = 0.0f;
    if (m > 0) {
        float sx = 0.0f, sy = 0.0f;
        for (int k = 0; k < m; k++) { sx += vx[k]; sy += vy[k]; }
        float mf = (float)m;
        float ccx = sx / mf, ccy = sy / mf;

        float ang[MAXV];
        for (int k = 0; k < m; k++) {
            vx[k] -= ccx;
            vy[k] -= ccy;
            ang[k] = atan2f(vy[k], vx[k]);
        }
        // stable insertion sort ascending by angle (matches jnp stable argsort)
        for (int k = 1; k < m; k++) {
            float a = ang[k], x = vx[k], y = vy[k];
            int j = k - 1;
            while (j >= 0 && ang[j] > a) {
                ang[j + 1] = ang[j]; vx[j + 1] = vx[j]; vy[j + 1] = vy[j];
                j--;
            }
            ang[j + 1] = a; vx[j + 1] = x; vy[j + 1] = y;
        }
        float s = 0.0f;
        for (int k = 0; k < m; k++) {
            int kn = (k + 1 == m) ? 0 : k + 1;
            s += vx[k] * vy[kn] - vy[k] * vx[kn];
        }
        inter_area = fabsf(s) * 0.5f;
    }

    float area1 = p_w * p_h;
    float area2 = t_w * t_h;
    float iou = inter_area / (area1 + area2 - inter_area);
    iou = fminf(fmaxf(iou, 0.0f), 1.0f);

    // horizontal enclosing box
    float ac1 = fabsf(c1), as1 = fabsf(s1);
    float ac2 = fabsf(c2), as2 = fabsf(s2);
    float dw1 = (p_w * ac1 + p_h * as1) * 0.5f;
    float dh1 = (p_w * as1 + p_h * ac1) * 0.5f;
    float dw2 = (t_w * ac2 + t_h * as2) * 0.5f;
    float dh2 = (t_w * as2 + t_h * ac2) * 0.5f;
    float en_w = fmaxf(fmaxf(p_cx + dw1, t_cx + dw2) - fminf(p_cx - dw1, t_cx - dw2), 0.0f);
    float en_h = fmaxf(fmaxf(p_cy + dh1, t_cy + dh2) - fminf(p_cy - dh1, t_cy - dh2), 0.0f);
    float c2v = en_w * en_w + en_h * en_h + MEPS;

    float dx = t_cx - p_cx, dy = t_cy - p_cy;
    float rho2 = dx * dx + dy * dy;

    const float factor = 0.40528473456935108577f;  // 4/pi^2
    float dv = atanf(t_w / (t_h + MEPS)) - atanf(p_w / (p_h + MEPS));
    float v = factor * dv * dv;
    float alpha = (iou > 0.5f) ? (v / (1.0f - iou + v + MEPS)) : 0.0f;

    float ciou = iou - (fminf(fmaxf(rho2 / c2v, 0.0f), 1.0f) + alpha * v);
    return (1.0f - ciou) * weight[i];
}

__global__ __launch_bounds__(TPB)
void obb_ciou_kernel(const float* __restrict__ pred,
                     const float* __restrict__ target,
                     const float* __restrict__ weight,
                     int N) {
    float loss = 0.0f;
    for (int i = blockIdx.x * TPB + threadIdx.x; i < N; i += gridDim.x * TPB) {
        loss += compute_loss(pred, target, weight, i);
    }
    // block reduction (deterministic)
    #pragma unroll
    for (int o = 16; o > 0; o >>= 1)
        loss += __shfl_down_sync(0xffffffffu, loss, o);
    __shared__ float sm[TPB / 32];
    if ((threadIdx.x & 31) == 0) sm[threadIdx.x >> 5] = loss;
    __syncthreads();
    if (threadIdx.x < TPB / 32) {
        float vsum = sm[threadIdx.x];
        #pragma unroll
        for (int o = TPB / 64; o > 0; o >>= 1)
            vsum += __shfl_down_sync(0xffu, vsum, o);
        if (threadIdx.x == 0) g_partials[blockIdx.x] = vsum;
    }
}

__global__ void reduce_kernel(float* __restrict__ out, int nblocks, float invN) {
    __shared__ float sm[512];
    int t = threadIdx.x;
    float s = 0.0f;
    for (int k = t; k < nblocks; k += 512) s += g_partials[k];
    sm[t] = s;
    __syncthreads();
    for (int o = 256; o > 0; o >>= 1) {
        if (t < o) sm[t] += sm[t + o];
        __syncthreads();
    }
    if (t == 0) out[0] = sm[0] * invN;
}

extern "C" void kernel_launch(void* const* d_in, const int* in_sizes, int n_in,
                              void* d_out, int out_size) {
    const float* pred   = (const float*)d_in[0];
    const float* target = (const float*)d_in[1];
    const float* weight = (const float*)d_in[2];
    int N = in_sizes[2];  // weight has N elements (pred/target have 5N)

    int nb = (N + TPB - 1) / TPB;
    if (nb > RED_MAX) nb = RED_MAX;
    if (nb < 1) nb = 1;

    obb_ciou_kernel<<<nb, TPB>>>(pred, target, weight, N);
    reduce_kernel<<<1, 512>>>((float*)d_out, nb, 1.0f / (float)N);
}

// round 4
// speedup vs baseline: 1.1729x; 1.1729x over previous
#include <cuda_runtime.h>
#include <math.h>

#define NEPS 1e-8f
#define MEPS 1e-6f
#define BTOL 1e-6f
#define MAXV 24
#define RED_MAX 4096
#define TPB 256

__device__ float g_partials[RED_MAX];
__device__ int   g_count = 0;

// Corner order matches reference: x4=[.5,-.5,-.5,.5]*w, y4=[-.5,-.5,.5,.5]*h
__device__ __forceinline__ void box_corners(float cx, float cy, float w, float h,
                                            float c, float s,
                                            float* X, float* Y) {
    float hw = 0.5f * w, hh = 0.5f * h;
    float xs0 =  hw, xs1 = -hw, xs2 = -hw, xs3 =  hw;
    float ys0 = -hh, ys1 = -hh, ys2 =  hh, ys3 =  hh;
    X[0] = xs0 * c - ys0 * s + cx;  Y[0] = xs0 * s + ys0 * c + cy;
    X[1] = xs1 * c - ys1 * s + cx;  Y[1] = xs1 * s + ys1 * c + cy;
    X[2] = xs2 * c - ys2 * s + cx;  Y[2] = xs2 * s + ys2 * c + cy;
    X[3] = xs3 * c - ys3 * s + cx;  Y[3] = xs3 * s + ys3 * c + cy;
}

// Monotone pseudo-angle, order-isomorphic to atan2(y,x) on (-pi, pi].
// Range [-2, 2]; wrap point at the negative-x axis like atan2.
__device__ __forceinline__ float pseudo_angle(float x, float y) {
    float t = __fdividef(y, fabsf(x) + fabsf(y));  // NaN only if x==y==0 (m==1 case, harmless)
    if (x >= 0.0f) return t;
    return (y >= 0.0f) ? (2.0f - t) : (-2.0f - t);
}

__device__ __forceinline__ float compute_loss(const float* __restrict__ pred,
                                              const float* __restrict__ target,
                                              const float* __restrict__ weight,
                                              int i) {
    const float* P = pred + (size_t)i * 5;
    const float* T = target + (size_t)i * 5;
    float p_cx = P[0], p_cy = P[1], p_w = P[2], p_h = P[3], p_a = P[4];
    float t_cx = T[0], t_cy = T[1], t_w = T[2], t_h = T[3], t_a = T[4];

    float c1, s1, c2, s2;
    __sincosf(p_a, &s1, &c1);
    __sincosf(t_a, &s2, &c2);

    float X1[4], Y1[4], X2[4], Y2[4];
    box_corners(p_cx, p_cy, p_w, p_h, c1, s1, X1, Y1);
    box_corners(t_cx, t_cy, t_w, t_h, c2, s2, X2, Y2);

    // Collect valid vertices in the reference's concatenation order:
    // corners1 (in box2), corners2 (in box1), intersections (k1-major).
    float vx[MAXV], vy[MAXV];
    int m = 0;

    // corners1 in box2:  a=C2[0], b=C2[1], d=C2[3]
    {
        float abx = X2[1] - X2[0], aby = Y2[1] - Y2[0];
        float adx = X2[3] - X2[0], ady = Y2[3] - Y2[0];
        float iab2 = __fdividef(1.0f, abx * abx + aby * aby);
        float iad2 = __fdividef(1.0f, adx * adx + ady * ady);
        #pragma unroll
        for (int k = 0; k < 4; k++) {
            float amx = X1[k] - X2[0], amy = Y1[k] - Y2[0];
            float pab = (abx * amx + aby * amy) * iab2;
            float pad = (adx * amx + ady * amy) * iad2;
            if (pab > -BTOL && pab < 1.0f + BTOL && pad > -BTOL && pad < 1.0f + BTOL) {
                vx[m] = X1[k]; vy[m] = Y1[k]; m++;
            }
        }
    }
    // corners2 in box1
    {
        float abx = X1[1] - X1[0], aby = Y1[1] - Y1[0];
        float adx = X1[3] - X1[0], ady = Y1[3] - Y1[0];
        float iab2 = __fdividef(1.0f, abx * abx + aby * aby);
        float iad2 = __fdividef(1.0f, adx * adx + ady * ady);
        #pragma unroll
        for (int k = 0; k < 4; k++) {
            float amx = X2[k] - X1[0], amy = Y2[k] - Y1[0];
            float pab = (abx * amx + aby * amy) * iab2;
            float pad = (adx * amx + ady * amy) * iad2;
            if (pab > -BTOL && pab < 1.0f + BTOL && pad > -BTOL && pad < 1.0f + BTOL) {
                vx[m] = X2[k]; vy[m] = Y2[k]; m++;
            }
        }
    }
    // segment intersections, k1 (box1 edge) major, k2 minor — matches reshape order
    #pragma unroll
    for (int k1 = 0; k1 < 4; k1++) {
        float x1 = X1[k1], y1 = Y1[k1];
        float x2 = X1[(k1 + 1) & 3], y2 = Y1[(k1 + 1) & 3];
        float ex = x2 - x1, ey = y2 - y1;
        #pragma unroll
        for (int k2 = 0; k2 < 4; k2++) {
            float x3 = X2[k2], y3 = Y2[k2];
            float x4 = X2[(k2 + 1) & 3], y4 = Y2[(k2 + 1) & 3];
            float fx = x4 - x3, fy = y4 - y3;
            float num   = fy * ex - fx * ey;
            float den_t = fx * (y1 - y3) - fy * (x1 - x3);
            float inum  = __fdividef(1.0f, num + NEPS);
            float t = den_t * inum;
            float den_u = ex * (y1 - y3) - ey * (x1 - x3);
            float u = -den_u * inum;
            bool ok = (num != 0.0f) &&
                      (t > 0.0f) && (t < 1.0f) &&
                      (u > 0.0f) && (u < 1.0f);
            if (ok) {
                vx[m] = fmaf(t, ex, x1);
                vy[m] = fmaf(t, ey, y1);
                m++;
            }
        }
    }

    // center, centered coords, pseudo-angles, stable sort, shoelace
    float inter_area = 0.0f;
    if (m > 0) {
        float sx = 0.0f, sy = 0.0f;
        for (int k = 0; k < m; k++) { sx += vx[k]; sy += vy[k]; }
        float imf = __fdividef(1.0f, (float)m);
        float ccx = sx * imf, ccy = sy * imf;

        float ang[MAXV];
        for (int k = 0; k < m; k++) {
            vx[k] -= ccx;
            vy[k] -= ccy;
            ang[k] = pseudo_angle(vx[k], vy[k]);
        }
        // stable insertion sort ascending (matches jnp stable argsort order)
        for (int k = 1; k < m; k++) {
            float a = ang[k], x = vx[k], y = vy[k];
            int j = k - 1;
            while (j >= 0 && ang[j] > a) {
                ang[j + 1] = ang[j]; vx[j + 1] = vx[j]; vy[j + 1] = vy[j];
                j--;
            }
            ang[j + 1] = a; vx[j + 1] = x; vy[j + 1] = y;
        }
        float s = 0.0f;
        for (int k = 0; k < m; k++) {
            int kn = (k + 1 == m) ? 0 : k + 1;
            s = fmaf(vx[k], vy[kn], s);
            s = fmaf(-vy[k], vx[kn], s);
        }
        inter_area = fabsf(s) * 0.5f;
    }

    float area1 = p_w * p_h;
    float area2 = t_w * t_h;
    float iou = __fdividef(inter_area, area1 + area2 - inter_area);
    iou = fminf(fmaxf(iou, 0.0f), 1.0f);

    // horizontal enclosing box
    float ac1 = fabsf(c1), as1 = fabsf(s1);
    float ac2 = fabsf(c2), as2 = fabsf(s2);
    float dw1 = (p_w * ac1 + p_h * as1) * 0.5f;
    float dh1 = (p_w * as1 + p_h * ac1) * 0.5f;
    float dw2 = (t_w * ac2 + t_h * as2) * 0.5f;
    float dh2 = (t_w * as2 + t_h * ac2) * 0.5f;
    float en_w = fmaxf(fmaxf(p_cx + dw1, t_cx + dw2) - fminf(p_cx - dw1, t_cx - dw2), 0.0f);
    float en_h = fmaxf(fmaxf(p_cy + dh1, t_cy + dh2) - fminf(p_cy - dh1, t_cy - dh2), 0.0f);
    float c2v = en_w * en_w + en_h * en_h + MEPS;

    float dx = t_cx - p_cx, dy = t_cy - p_cy;
    float rho2 = dx * dx + dy * dy;

    const float factor = 0.40528473456935108577f;  // 4/pi^2
    float dv = atanf(__fdividef(t_w, t_h + MEPS)) - atanf(__fdividef(p_w, p_h + MEPS));
    float v = factor * dv * dv;
    float alpha = (iou > 0.5f) ? __fdividef(v, 1.0f - iou + v + MEPS) : 0.0f;

    float ciou = iou - (fminf(fmaxf(__fdividef(rho2, c2v), 0.0f), 1.0f) + alpha * v);
    return (1.0f - ciou) * weight[i];
}

__global__ __launch_bounds__(TPB)
void obb_ciou_kernel(const float* __restrict__ pred,
                     const float* __restrict__ target,
                     const float* __restrict__ weight,
                     float* __restrict__ out,
                     int N, float invN) {
    float loss = 0.0f;
    for (int i = blockIdx.x * TPB + threadIdx.x; i < N; i += gridDim.x * TPB) {
        loss += compute_loss(pred, target, weight, i);
    }
    // block reduction (deterministic fixed order)
    #pragma unroll
    for (int o = 16; o > 0; o >>= 1)
        loss += __shfl_down_sync(0xffffffffu, loss, o);
    __shared__ float sm[TPB / 32];
    __shared__ bool isLast;
    if ((threadIdx.x & 31) == 0) sm[threadIdx.x >> 5] = loss;
    __syncthreads();
    if (threadIdx.x < 32) {
        float vsum = (threadIdx.x < TPB / 32) ? sm[threadIdx.x] : 0.0f;
        #pragma unroll
        for (int o = TPB / 64; o > 0; o >>= 1)
            vsum += __shfl_down_sync(0xffffffffu, vsum, o);
        if (threadIdx.x == 0) {
            g_partials[blockIdx.x] = vsum;
            __threadfence();
            int prev = atomicAdd(&g_count, 1);
            isLast = (prev == (int)gridDim.x - 1);
        }
    }
    __syncthreads();
    if (isLast) {
        int nb = gridDim.x;
        float s = 0.0f;
        for (int k = threadIdx.x; k < nb; k += TPB) s += g_partials[k];
        #pragma unroll
        for (int o = 16; o > 0; o >>= 1)
            s += __shfl_down_sync(0xffffffffu, s, o);
        if ((threadIdx.x & 31) == 0) sm[threadIdx.x >> 5] = s;
        __syncthreads();
        if (threadIdx.x < 32) {
            float vs = (threadIdx.x < TPB / 32) ? sm[threadIdx.x] : 0.0f;
            #pragma unroll
            for (int o = TPB / 64; o > 0; o >>= 1)
                vs += __shfl_down_sync(0xffffffffu, vs, o);
            if (threadIdx.x == 0) {
                out[0] = vs * invN;
                g_count = 0;   // reset for next graph replay
            }
        }
    }
}

extern "C" void kernel_launch(void* const* d_in, const int* in_sizes, int n_in,
                              void* d_out, int out_size) {
    const float* pred   = (const float*)d_in[0];
    const float* target = (const float*)d_in[1];
    const float* weight = (const float*)d_in[2];
    int N = in_sizes[2];  // weight has N elements

    int nb = (N + TPB - 1) / TPB;
    if (nb > RED_MAX) nb = RED_MAX;
    if (nb < 1) nb = 1;

    obb_ciou_kernel<<<nb, TPB>>>(pred, target, weight, (float*)d_out,
                                 N, 1.0f / (float)N);
}

// round 6
// speedup vs baseline: 1.2027x; 1.0254x over previous
#include <cuda_runtime.h>
#include <math.h>

#define NEPS 1e-8f
#define MEPS 1e-6f
#define BTOL 1e-6f
#define MAXV 16
#define RED_MAX 4096
#define TPB 256

__device__ float g_partials[RED_MAX];
__device__ int   g_count = 0;

// Corner order matches reference: x4=[.5,-.5,-.5,.5]*w, y4=[-.5,-.5,.5,.5]*h
__device__ __forceinline__ void box_corners(float cx, float cy, float w, float h,
                                            float c, float s,
                                            float* X, float* Y) {
    float hw = 0.5f * w, hh = 0.5f * h;
    float xs0 =  hw, xs1 = -hw, xs2 = -hw, xs3 =  hw;
    float ys0 = -hh, ys1 = -hh, ys2 =  hh, ys3 =  hh;
    X[0] = xs0 * c - ys0 * s + cx;  Y[0] = xs0 * s + ys0 * c + cy;
    X[1] = xs1 * c - ys1 * s + cx;  Y[1] = xs1 * s + ys1 * c + cy;
    X[2] = xs2 * c - ys2 * s + cx;  Y[2] = xs2 * s + ys2 * c + cy;
    X[3] = xs3 * c - ys3 * s + cx;  Y[3] = xs3 * s + ys3 * c + cy;
}

// Monotone pseudo-angle, order-isomorphic to atan2(y,x) on (-pi, pi].
__device__ __forceinline__ float pseudo_angle(float x, float y) {
    float t = __fdividef(y, fabsf(x) + fabsf(y));
    if (x >= 0.0f) return t;
    return (y >= 0.0f) ? (2.0f - t) : (-2.0f - t);
}

// Order-preserving float -> uint32 (total order matching < on floats)
__device__ __forceinline__ unsigned int ordered_bits(float f) {
    unsigned int u = __float_as_uint(f);
    return ((int)u < 0) ? ~u : (u | 0x80000000u);
}

__global__ __launch_bounds__(TPB)
void obb_ciou_kernel(const float* __restrict__ pred,
                     const float* __restrict__ target,
                     const float* __restrict__ weight,
                     float* __restrict__ out,
                     int N, float invN) {
    __shared__ float s_vx[MAXV][TPB];   // 16KB
    __shared__ float s_vy[MAXV][TPB];   // 16KB
    const int tid = threadIdx.x;

    float loss = 0.0f;
    for (int i = blockIdx.x * TPB + tid; i < N; i += gridDim.x * TPB) {
        const float* P = pred + (size_t)i * 5;
        const float* T = target + (size_t)i * 5;
        float p_cx = P[0], p_cy = P[1], p_w = P[2], p_h = P[3], p_a = P[4];
        float t_cx = T[0], t_cy = T[1], t_w = T[2], t_h = T[3], t_a = T[4];

        float c1, s1, c2, s2;
        __sincosf(p_a, &s1, &c1);
        __sincosf(t_a, &s2, &c2);

        float X1[4], Y1[4], X2[4], Y2[4];
        box_corners(p_cx, p_cy, p_w, p_h, c1, s1, X1, Y1);
        box_corners(t_cx, t_cy, t_w, t_h, c2, s2, X2, Y2);

        // ---- collect valid vertices (reference concatenation order) ----
        int m = 0;
        float sx = 0.0f, sy = 0.0f;

        // corners1 in box2: a=C2[0], b=C2[1], d=C2[3]
        {
            float abx = X2[1] - X2[0], aby = Y2[1] - Y2[0];
            float adx = X2[3] - X2[0], ady = Y2[3] - Y2[0];
            float iab2 = __fdividef(1.0f, abx * abx + aby * aby);
            float iad2 = __fdividef(1.0f, adx * adx + ady * ady);
            #pragma unroll
            for (int k = 0; k < 4; k++) {
                float amx = X1[k] - X2[0], amy = Y1[k] - Y2[0];
                float pab = (abx * amx + aby * amy) * iab2;
                float pad = (adx * amx + ady * amy) * iad2;
                if (pab > -BTOL && pab < 1.0f + BTOL && pad > -BTOL && pad < 1.0f + BTOL) {
                    s_vx[m][tid] = X1[k]; s_vy[m][tid] = Y1[k];
                    sx += X1[k]; sy += Y1[k]; m++;
                }
            }
        }
        // corners2 in box1
        {
            float abx = X1[1] - X1[0], aby = Y1[1] - Y1[0];
            float adx = X1[3] - X1[0], ady = Y1[3] - Y1[0];
            float iab2 = __fdividef(1.0f, abx * abx + aby * aby);
            float iad2 = __fdividef(1.0f, adx * adx + ady * ady);
            #pragma unroll
            for (int k = 0; k < 4; k++) {
                float amx = X2[k] - X1[0], amy = Y2[k] - Y1[0];
                float pab = (abx * amx + aby * amy) * iab2;
                float pad = (adx * amx + ady * amy) * iad2;
                if (pab > -BTOL && pab < 1.0f + BTOL && pad > -BTOL && pad < 1.0f + BTOL) {
                    s_vx[m][tid] = X2[k]; s_vy[m][tid] = Y2[k];
                    sx += X2[k]; sy += Y2[k]; m++;
                }
            }
        }
        // segment intersections, k1-major (matches reshape order)
        #pragma unroll
        for (int k1 = 0; k1 < 4; k1++) {
            float x1 = X1[k1], y1 = Y1[k1];
            float ex = X1[(k1 + 1) & 3] - x1, ey = Y1[(k1 + 1) & 3] - y1;
            #pragma unroll
            for (int k2 = 0; k2 < 4; k2++) {
                float x3 = X2[k2], y3 = Y2[k2];
                float fx = X2[(k2 + 1) & 3] - x3, fy = Y2[(k2 + 1) & 3] - y3;
                float num   = fy * ex - fx * ey;
                float den_t = fx * (y1 - y3) - fy * (x1 - x3);
                float inum  = __fdividef(1.0f, num + NEPS);
                float t = den_t * inum;
                float den_u = ex * (y1 - y3) - ey * (x1 - x3);
                float u = -den_u * inum;
                bool ok = (num != 0.0f) &&
                          (t > 0.0f) && (t < 1.0f) &&
                          (u > 0.0f) && (u < 1.0f);
                if (ok) {
                    float ix = fmaf(t, ex, x1);
                    float iy = fmaf(t, ey, y1);
                    s_vx[m][tid] = ix; s_vy[m][tid] = iy;
                    sx += ix; sy += iy; m++;
                }
            }
        }

        // ---- centroid, keys, stable sort, shoelace ----
        float inter_area = 0.0f;
        if (m > 2) {
            float imf = __fdividef(1.0f, (float)m);
            float ccx = sx * imf, ccy = sy * imf;

            unsigned long long key[MAXV];
            for (int k = 0; k < m; k++) {
                float x = s_vx[k][tid] - ccx;
                float y = s_vy[k][tid] - ccy;
                unsigned int u = ordered_bits(pseudo_angle(x, y));
                key[k] = ((unsigned long long)u << 8) | (unsigned int)k;
            }
            // stable ascending insertion sort on packed keys
            for (int k = 1; k < m; k++) {
                unsigned long long kv = key[k];
                int j = k - 1;
                while (j >= 0 && key[j] > kv) { key[j + 1] = key[j]; j--; }
                key[j + 1] = kv;
            }
            int i0 = (int)(key[0] & 0xFF);
            float fx0 = s_vx[i0][tid] - ccx, fy0 = s_vy[i0][tid] - ccy;
            float px = fx0, py = fy0;
            float s = 0.0f;
            for (int k = 1; k < m; k++) {
                int idx = (int)(key[k] & 0xFF);
                float x = s_vx[idx][tid] - ccx, y = s_vy[idx][tid] - ccy;
                s = fmaf(px, y, s);
                s = fmaf(-py, x, s);
                px = x; py = y;
            }
            s = fmaf(px, fy0, s);
            s = fmaf(-py, fx0, s);
            inter_area = fabsf(s) * 0.5f;
        }

        float area1 = p_w * p_h;
        float area2 = t_w * t_h;
        float iou = __fdividef(inter_area, area1 + area2 - inter_area);
        iou = fminf(fmaxf(iou, 0.0f), 1.0f);

        float ac1 = fabsf(c1), as1 = fabsf(s1);
        float ac2 = fabsf(c2), as2 = fabsf(s2);
        float dw1 = (p_w * ac1 + p_h * as1) * 0.5f;
        float dh1 = (p_w * as1 + p_h * ac1) * 0.5f;
        float dw2 = (t_w * ac2 + t_h * as2) * 0.5f;
        float dh2 = (t_w * as2 + t_h * ac2) * 0.5f;
        float en_w = fmaxf(fmaxf(p_cx + dw1, t_cx + dw2) - fminf(p_cx - dw1, t_cx - dw2), 0.0f);
        float en_h = fmaxf(fmaxf(p_cy + dh1, t_cy + dh2) - fminf(p_cy - dh1, t_cy - dh2), 0.0f);
        float c2v = en_w * en_w + en_h * en_h + MEPS;

        float dx = t_cx - p_cx, dy = t_cy - p_cy;
        float rho2 = dx * dx + dy * dy;

        const float factor = 0.40528473456935108577f;  // 4/pi^2
        float dv = atanf(__fdividef(t_w, t_h + MEPS)) - atanf(__fdividef(p_w, p_h + MEPS));
        float v = factor * dv * dv;
        float alpha = (iou > 0.5f) ? __fdividef(v, 1.0f - iou + v + MEPS) : 0.0f;

        float ciou = iou - (fminf(fmaxf(__fdividef(rho2, c2v), 0.0f), 1.0f) + alpha * v);
        loss += (1.0f - ciou) * weight[i];
    }

    // ---- deterministic fixed-order reduction (proven in R4) ----
    #pragma unroll
    for (int o = 16; o > 0; o >>= 1)
        loss += __shfl_down_sync(0xffffffffu, loss, o);
    __shared__ float sm[TPB / 32];
    __shared__ bool isLast;
    if ((tid & 31) == 0) sm[tid >> 5] = loss;
    __syncthreads();
    if (tid < 32) {
        float vsum = (tid < TPB / 32) ? sm[tid] : 0.0f;
        #pragma unroll
        for (int o = TPB / 64; o > 0; o >>= 1)
            vsum += __shfl_down_sync(0xffffffffu, vsum, o);
        if (tid == 0) {
            g_partials[blockIdx.x] = vsum;
            __threadfence();
            int prev = atomicAdd(&g_count, 1);
            isLast = (prev == (int)gridDim.x - 1);
        }
    }
    __syncthreads();
    if (isLast) {
        int nb = gridDim.x;
        float s = 0.0f;
        for (int k = tid; k < nb; k += TPB) s += g_partials[k];
        #pragma unroll
        for (int o = 16; o > 0; o >>= 1)
            s += __shfl_down_sync(0xffffffffu, s, o);
        if ((tid & 31) == 0) sm[tid >> 5] = s;
        __syncthreads();
        if (tid < 32) {
            float vs = (tid < TPB / 32) ? sm[tid] : 0.0f;
            #pragma unroll
            for (int o = TPB / 64; o > 0; o >>= 1)
                vs += __shfl_down_sync(0xffffffffu, vs, o);
            if (tid == 0) {
                out[0] = vs * invN;
                g_count = 0;   // reset for next graph replay
            }
        }
    }
}

extern "C" void kernel_launch(void* const* d_in, const int* in_sizes, int n_in,
                              void* d_out, int out_size) {
    const float* pred   = (const float*)d_in[0];
    const float* target = (const float*)d_in[1];
    const float* weight = (const float*)d_in[2];
    int N = in_sizes[2];  // weight has N elements

    int nb = (N + TPB - 1) / TPB;
    if (nb > RED_MAX) nb = RED_MAX;
    if (nb < 1) nb = 1;

    obb_ciou_kernel<<<nb, TPB>>>(pred, target, weight, (float*)d_out,
                                 N, 1.0f / (float)N);
}

// round 7
// speedup vs baseline: 1.3926x; 1.1579x over previous
#include <cuda_runtime.h>
#include <math.h>

#define NEPS 1e-8f
#define MEPS 1e-6f
#define BTOL 1e-6f
#define MAXV 16
#define RED_MAX 4096
#define TPB 256

__device__ float g_partials[RED_MAX];
__device__ int   g_count = 0;

// Corner order matches reference: x4=[.5,-.5,-.5,.5]*w, y4=[-.5,-.5,.5,.5]*h
__device__ __forceinline__ void box_corners(float cx, float cy, float w, float h,
                                            float c, float s,
                                            float* X, float* Y) {
    float hw = 0.5f * w, hh = 0.5f * h;
    float xs0 =  hw, xs1 = -hw, xs2 = -hw, xs3 =  hw;
    float ys0 = -hh, ys1 = -hh, ys2 =  hh, ys3 =  hh;
    X[0] = xs0 * c - ys0 * s + cx;  Y[0] = xs0 * s + ys0 * c + cy;
    X[1] = xs1 * c - ys1 * s + cx;  Y[1] = xs1 * s + ys1 * c + cy;
    X[2] = xs2 * c - ys2 * s + cx;  Y[2] = xs2 * s + ys2 * c + cy;
    X[3] = xs3 * c - ys3 * s + cx;  Y[3] = xs3 * s + ys3 * c + cy;
}

// Monotone pseudo-angle, order-isomorphic to atan2(y,x) on (-pi, pi].
__device__ __forceinline__ float pseudo_angle(float x, float y) {
    float t = __fdividef(y, fabsf(x) + fabsf(y));
    if (x >= 0.0f) return t;
    return (y >= 0.0f) ? (2.0f - t) : (-2.0f - t);
}

// Order-preserving float -> uint32
__device__ __forceinline__ unsigned int ordered_bits(float f) {
    unsigned int u = __float_as_uint(f);
    return ((int)u < 0) ? ~u : (u | 0x80000000u);
}

__global__ __launch_bounds__(TPB, 4)
void obb_ciou_kernel(const float* __restrict__ pred,
                     const float* __restrict__ target,
                     const float* __restrict__ weight,
                     float* __restrict__ out,
                     int N, float invN) {
    __shared__ float s_vx[MAXV][TPB];   // 16KB
    __shared__ float s_vy[MAXV][TPB];   // 16KB
    const int tid = threadIdx.x;

    float loss = 0.0f;
    for (int i = blockIdx.x * TPB + tid; i < N; i += gridDim.x * TPB) {
        const float* P = pred + (size_t)i * 5;
        const float* T = target + (size_t)i * 5;
        float p_cx = P[0], p_cy = P[1], p_w = P[2], p_h = P[3], p_a = P[4];
        float t_cx = T[0], t_cy = T[1], t_w = T[2], t_h = T[3], t_a = T[4];

        float c1, s1, c2, s2;
        __sincosf(p_a, &s1, &c1);
        __sincosf(t_a, &s2, &c2);

        float X1[4], Y1[4], X2[4], Y2[4];
        box_corners(p_cx, p_cy, p_w, p_h, c1, s1, X1, Y1);
        box_corners(t_cx, t_cy, t_w, t_h, c2, s2, X2, Y2);

        // ---- collect valid vertices (reference concatenation order) ----
        int m = 0;
        float sx = 0.0f, sy = 0.0f;

        // corners1 in box2: a=C2[0], b=C2[1], d=C2[3]   (division-free tests)
        {
            float abx = X2[1] - X2[0], aby = Y2[1] - Y2[0];
            float adx = X2[3] - X2[0], ady = Y2[3] - Y2[0];
            float ab2 = abx * abx + aby * aby;
            float ad2 = adx * adx + ady * ady;
            float ab_lo = -BTOL * ab2, ab_hi = (1.0f + BTOL) * ab2;
            float ad_lo = -BTOL * ad2, ad_hi = (1.0f + BTOL) * ad2;
            #pragma unroll
            for (int k = 0; k < 4; k++) {
                float amx = X1[k] - X2[0], amy = Y1[k] - Y2[0];
                float dab = abx * amx + aby * amy;
                float dad = adx * amx + ady * amy;
                if (dab > ab_lo && dab < ab_hi && dad > ad_lo && dad < ad_hi) {
                    s_vx[m][tid] = X1[k]; s_vy[m][tid] = Y1[k];
                    sx += X1[k]; sy += Y1[k]; m++;
                }
            }
        }
        // corners2 in box1
        {
            float abx = X1[1] - X1[0], aby = Y1[1] - Y1[0];
            float adx = X1[3] - X1[0], ady = Y1[3] - Y1[0];
            float ab2 = abx * abx + aby * aby;
            float ad2 = adx * adx + ady * ady;
            float ab_lo = -BTOL * ab2, ab_hi = (1.0f + BTOL) * ab2;
            float ad_lo = -BTOL * ad2, ad_hi = (1.0f + BTOL) * ad2;
            #pragma unroll
            for (int k = 0; k < 4; k++) {
                float amx = X2[k] - X1[0], amy = Y2[k] - Y1[0];
                float dab = abx * amx + aby * amy;
                float dad = adx * amx + ady * amy;
                if (dab > ab_lo && dab < ab_hi && dad > ad_lo && dad < ad_hi) {
                    s_vx[m][tid] = X2[k]; s_vy[m][tid] = Y2[k];
                    sx += X2[k]; sy += Y2[k]; m++;
                }
            }
        }
        // segment intersections, k1-major (matches reshape order)
        #pragma unroll
        for (int k1 = 0; k1 < 4; k1++) {
            float x1 = X1[k1], y1 = Y1[k1];
            float ex = X1[(k1 + 1) & 3] - x1, ey = Y1[(k1 + 1) & 3] - y1;
            #pragma unroll
            for (int k2 = 0; k2 < 4; k2++) {
                float x3 = X2[k2], y3 = Y2[k2];
                float fx = X2[(k2 + 1) & 3] - x3, fy = Y2[(k2 + 1) & 3] - y3;
                float num   = fy * ex - fx * ey;
                float den_t = fx * (y1 - y3) - fy * (x1 - x3);
                float inum  = __fdividef(1.0f, num + NEPS);
                float t = den_t * inum;
                float den_u = ex * (y1 - y3) - ey * (x1 - x3);
                float u = -den_u * inum;
                bool ok = (num != 0.0f) &&
                          (t > 0.0f) && (t < 1.0f) &&
                          (u > 0.0f) && (u < 1.0f);
                if (ok) {
                    float ix = fmaf(t, ex, x1);
                    float iy = fmaf(t, ey, y1);
                    s_vx[m][tid] = ix; s_vy[m][tid] = iy;
                    sx += ix; sy += iy; m++;
                }
            }
        }

        // ---- centroid, packed 32-bit keys, stable sort, shoelace ----
        float inter_area = 0.0f;
        if (m > 2) {
            float imf = __fdividef(1.0f, (float)m);
            float ccx = sx * imf, ccy = sy * imf;

            unsigned int key[MAXV];
            for (int k = 0; k < m; k++) {
                float x = s_vx[k][tid] - ccx;
                float y = s_vy[k][tid] - ccy;
                unsigned int u = ordered_bits(pseudo_angle(x, y));
                key[k] = (u & 0xFFFFFFE0u) | (unsigned int)k;   // 27-bit angle | 5-bit idx
            }
            // stable ascending insertion sort
            for (int k = 1; k < m; k++) {
                unsigned int kv = key[k];
                int j = k - 1;
                while (j >= 0 && key[j] > kv) { key[j + 1] = key[j]; j--; }
                key[j + 1] = kv;
            }
            int i0 = (int)(key[0] & 0x1F);
            float fx0 = s_vx[i0][tid] - ccx, fy0 = s_vy[i0][tid] - ccy;
            float px = fx0, py = fy0;
            float s = 0.0f;
            for (int k = 1; k < m; k++) {
                int idx = (int)(key[k] & 0x1F);
                float x = s_vx[idx][tid] - ccx, y = s_vy[idx][tid] - ccy;
                s = fmaf(px, y, s);
                s = fmaf(-py, x, s);
                px = x; py = y;
            }
            s = fmaf(px, fy0, s);
            s = fmaf(-py, fx0, s);
            inter_area = fabsf(s) * 0.5f;
        }

        float area1 = p_w * p_h;
        float area2 = t_w * t_h;
        float iou = __fdividef(inter_area, area1 + area2 - inter_area);
        iou = fminf(fmaxf(iou, 0.0f), 1.0f);

        float ac1 = fabsf(c1), as1 = fabsf(s1);
        float ac2 = fabsf(c2), as2 = fabsf(s2);
        float dw1 = (p_w * ac1 + p_h * as1) * 0.5f;
        float dh1 = (p_w * as1 + p_h * ac1) * 0.5f;
        float dw2 = (t_w * ac2 + t_h * as2) * 0.5f;
        float dh2 = (t_w * as2 + t_h * ac2) * 0.5f;
        float en_w = fmaxf(fmaxf(p_cx + dw1, t_cx + dw2) - fminf(p_cx - dw1, t_cx - dw2), 0.0f);
        float en_h = fmaxf(fmaxf(p_cy + dh1, t_cy + dh2) - fminf(p_cy - dh1, t_cy - dh2), 0.0f);
        float c2v = en_w * en_w + en_h * en_h + MEPS;

        float dx = t_cx - p_cx, dy = t_cy - p_cy;
        float rho2 = dx * dx + dy * dy;

        const float factor = 0.40528473456935108577f;  // 4/pi^2
        float dv = atanf(__fdividef(t_w, t_h + MEPS)) - atanf(__fdividef(p_w, p_h + MEPS));
        float v = factor * dv * dv;
        float alpha = (iou > 0.5f) ? __fdividef(v, 1.0f - iou + v + MEPS) : 0.0f;

        float ciou = iou - (fminf(fmaxf(__fdividef(rho2, c2v), 0.0f), 1.0f) + alpha * v);
        loss += (1.0f - ciou) * weight[i];
    }

    // ---- deterministic fixed-order reduction ----
    #pragma unroll
    for (int o = 16; o > 0; o >>= 1)
        loss += __shfl_down_sync(0xffffffffu, loss, o);
    __shared__ float sm[TPB / 32];
    __shared__ bool isLast;
    if ((tid & 31) == 0) sm[tid >> 5] = loss;
    __syncthreads();
    if (tid < 32) {
        float vsum = (tid < TPB / 32) ? sm[tid] : 0.0f;
        #pragma unroll
        for (int o = TPB / 64; o > 0; o >>= 1)
            vsum += __shfl_down_sync(0xffffffffu, vsum, o);
        if (tid == 0) {
            g_partials[blockIdx.x] = vsum;
            __threadfence();
            int prev = atomicAdd(&g_count, 1);
            isLast = (prev == (int)gridDim.x - 1);
        }
    }
    __syncthreads();
    if (isLast) {
        int nb = gridDim.x;
        float s = 0.0f;
        for (int k = tid; k < nb; k += TPB) s += g_partials[k];
        #pragma unroll
        for (int o = 16; o > 0; o >>= 1)
            s += __shfl_down_sync(0xffffffffu, s, o);
        if ((tid & 31) == 0) sm[tid >> 5] = s;
        __syncthreads();
        if (tid < 32) {
            float vs = (tid < TPB / 32) ? sm[tid] : 0.0f;
            #pragma unroll
            for (int o = TPB / 64; o > 0; o >>= 1)
                vs += __shfl_down_sync(0xffffffffu, vs, o);
            if (tid == 0) {
                out[0] = vs * invN;
                g_count = 0;   // reset for next graph replay
            }
        }
    }
}

extern "C" void kernel_launch(void* const* d_in, const int* in_sizes, int n_in,
                              void* d_out, int out_size) {
    const float* pred   = (const float*)d_in[0];
    const float* target = (const float*)d_in[1];
    const float* weight = (const float*)d_in[2];
    int N = in_sizes[2];  // weight has N elements

    int nb = (N + TPB - 1) / TPB;
    if (nb > RED_MAX) nb = RED_MAX;
    if (nb < 1) nb = 1;

    obb_ciou_kernel<<<nb, TPB>>>(pred, target, weight, (float*)d_out,
                                 N, 1.0f / (float)N);
}

// round 8
// speedup vs baseline: 1.4619x; 1.0498x over previous
#include <cuda_runtime.h>
#include <math.h>

#define NEPS 1e-8f
#define MEPS 1e-6f
#define BTOL 1e-6f
#define MAXV 16
#define RED_MAX 4096
#define TPB 256

__device__ float g_partials[RED_MAX];
__device__ int   g_count = 0;

// Corner order matches reference: x4=[.5,-.5,-.5,.5]*w, y4=[-.5,-.5,.5,.5]*h
__device__ __forceinline__ void box_corners(float cx, float cy, float w, float h,
                                            float c, float s,
                                            float* X, float* Y) {
    float hw = 0.5f * w, hh = 0.5f * h;
    float xs0 =  hw, xs1 = -hw, xs2 = -hw, xs3 =  hw;
    float ys0 = -hh, ys1 = -hh, ys2 =  hh, ys3 =  hh;
    X[0] = xs0 * c - ys0 * s + cx;  Y[0] = xs0 * s + ys0 * c + cy;
    X[1] = xs1 * c - ys1 * s + cx;  Y[1] = xs1 * s + ys1 * c + cy;
    X[2] = xs2 * c - ys2 * s + cx;  Y[2] = xs2 * s + ys2 * c + cy;
    X[3] = xs3 * c - ys3 * s + cx;  Y[3] = xs3 * s + ys3 * c + cy;
}

// Monotone pseudo-angle, order-isomorphic to atan2(y,x) on (-pi, pi].
__device__ __forceinline__ float pseudo_angle(float x, float y) {
    float t = __fdividef(y, fabsf(x) + fabsf(y));
    if (x >= 0.0f) return t;
    return (y >= 0.0f) ? (2.0f - t) : (-2.0f - t);
}

// Order-preserving float -> uint32
__device__ __forceinline__ unsigned int ordered_bits(float f) {
    unsigned int u = __float_as_uint(f);
    return ((int)u < 0) ? ~u : (u | 0x80000000u);
}

__global__ __launch_bounds__(TPB, 4)
void obb_ciou_kernel(const float* __restrict__ pred,
                     const float* __restrict__ target,
                     const float* __restrict__ weight,
                     float* __restrict__ out,
                     int N, float invN) {
    __shared__ float2 s_v[MAXV][TPB];   // 32KB; row stride 2048B -> lane-invariant banks
    const int tid = threadIdx.x;
    float2* const col = &s_v[0][tid];   // row k at col[k*TPB]

    float loss = 0.0f;
    for (int i = blockIdx.x * TPB + tid; i < N; i += gridDim.x * TPB) {
        const float* P = pred + (size_t)i * 5;
        const float* T = target + (size_t)i * 5;
        float p_cx = P[0], p_cy = P[1], p_w = P[2], p_h = P[3], p_a = P[4];
        float t_cx = T[0], t_cy = T[1], t_w = T[2], t_h = T[3], t_a = T[4];

        float c1, s1, c2, s2;
        __sincosf(p_a, &s1, &c1);
        __sincosf(t_a, &s2, &c2);

        float X1[4], Y1[4], X2[4], Y2[4];
        box_corners(p_cx, p_cy, p_w, p_h, c1, s1, X1, Y1);
        box_corners(t_cx, t_cy, t_w, t_h, c2, s2, X2, Y2);

        // ---- collect valid vertices (reference concatenation order) ----
        int m = 0;
        float sx = 0.0f, sy = 0.0f;

        // corners1 in box2: a=C2[0], b=C2[1], d=C2[3]   (division-free tests)
        {
            float abx = X2[1] - X2[0], aby = Y2[1] - Y2[0];
            float adx = X2[3] - X2[0], ady = Y2[3] - Y2[0];
            float ab2 = abx * abx + aby * aby;
            float ad2 = adx * adx + ady * ady;
            float ab_lo = -BTOL * ab2, ab_hi = (1.0f + BTOL) * ab2;
            float ad_lo = -BTOL * ad2, ad_hi = (1.0f + BTOL) * ad2;
            #pragma unroll
            for (int k = 0; k < 4; k++) {
                float amx = X1[k] - X2[0], amy = Y1[k] - Y2[0];
                float dab = abx * amx + aby * amy;
                float dad = adx * amx + ady * amy;
                if (dab > ab_lo && dab < ab_hi && dad > ad_lo && dad < ad_hi) {
                    col[m * TPB] = make_float2(X1[k], Y1[k]);
                    sx += X1[k]; sy += Y1[k]; m++;
                }
            }
        }
        // corners2 in box1
        {
            float abx = X1[1] - X1[0], aby = Y1[1] - Y1[0];
            float adx = X1[3] - X1[0], ady = Y1[3] - Y1[0];
            float ab2 = abx * abx + aby * aby;
            float ad2 = adx * adx + ady * ady;
            float ab_lo = -BTOL * ab2, ab_hi = (1.0f + BTOL) * ab2;
            float ad_lo = -BTOL * ad2, ad_hi = (1.0f + BTOL) * ad2;
            #pragma unroll
            for (int k = 0; k < 4; k++) {
                float amx = X2[k] - X1[0], amy = Y2[k] - Y1[0];
                float dab = abx * amx + aby * amy;
                float dad = adx * amx + ady * amy;
                if (dab > ab_lo && dab < ab_hi && dad > ad_lo && dad < ad_hi) {
                    col[m * TPB] = make_float2(X2[k], Y2[k]);
                    sx += X2[k]; sy += Y2[k]; m++;
                }
            }
        }
        // segment intersections, k1-major (matches reshape order)
        #pragma unroll
        for (int k1 = 0; k1 < 4; k1++) {
            float x1 = X1[k1], y1 = Y1[k1];
            float ex = X1[(k1 + 1) & 3] - x1, ey = Y1[(k1 + 1) & 3] - y1;
            #pragma unroll
            for (int k2 = 0; k2 < 4; k2++) {
                float x3 = X2[k2], y3 = Y2[k2];
                float fx = X2[(k2 + 1) & 3] - x3, fy = Y2[(k2 + 1) & 3] - y3;
                float num   = fy * ex - fx * ey;
                float den_t = fx * (y1 - y3) - fy * (x1 - x3);
                float inum  = __fdividef(1.0f, num + NEPS);
                float t = den_t * inum;
                float den_u = ex * (y1 - y3) - ey * (x1 - x3);
                float u = -den_u * inum;
                bool ok = (num != 0.0f) &&
                          (t > 0.0f) && (t < 1.0f) &&
                          (u > 0.0f) && (u < 1.0f);
                if (ok) {
                    float ix = fmaf(t, ex, x1);
                    float iy = fmaf(t, ey, y1);
                    col[m * TPB] = make_float2(ix, iy);
                    sx += ix; sy += iy; m++;
                }
            }
        }

        // ---- centroid -> angle keys, stable sort, raw-coordinate shoelace ----
        float inter_area = 0.0f;
        if (m > 2) {
            float imf = __fdividef(1.0f, (float)m);
            float ccx = sx * imf, ccy = sy * imf;

            unsigned int key[MAXV];
            for (int k = 0; k < m; k++) {
                float2 v = col[k * TPB];
                unsigned int u = ordered_bits(pseudo_angle(v.x - ccx, v.y - ccy));
                key[k] = (u & 0xFFFFFFE0u) | (unsigned int)k;   // 27-bit angle | 5-bit idx
            }
            // stable ascending insertion sort
            for (int k = 1; k < m; k++) {
                unsigned int kv = key[k];
                int j = k - 1;
                while (j >= 0 && key[j] > kv) { key[j + 1] = key[j]; j--; }
                key[j + 1] = kv;
            }
            // shoelace over raw coords (translation-invariant on closed ring)
            float2 f0 = col[(int)(key[0] & 0x1F) * TPB];
            float px = f0.x, py = f0.y;
            float s = 0.0f;
            for (int k = 1; k < m; k++) {
                float2 v = col[(int)(key[k] & 0x1F) * TPB];
                s = fmaf(px, v.y, s);
                s = fmaf(-py, v.x, s);
                px = v.x; py = v.y;
            }
            s = fmaf(px, f0.y, s);
            s = fmaf(-py, f0.x, s);
            inter_area = fabsf(s) * 0.5f;
        }

        float area1 = p_w * p_h;
        float area2 = t_w * t_h;
        float iou = __fdividef(inter_area, area1 + area2 - inter_area);
        iou = fminf(fmaxf(iou, 0.0f), 1.0f);

        float ac1 = fabsf(c1), as1 = fabsf(s1);
        float ac2 = fabsf(c2), as2 = fabsf(s2);
        float dw1 = (p_w * ac1 + p_h * as1) * 0.5f;
        float dh1 = (p_w * as1 + p_h * ac1) * 0.5f;
        float dw2 = (t_w * ac2 + t_h * as2) * 0.5f;
        float dh2 = (t_w * as2 + t_h * ac2) * 0.5f;
        float en_w = fmaxf(fmaxf(p_cx + dw1, t_cx + dw2) - fminf(p_cx - dw1, t_cx - dw2), 0.0f);
        float en_h = fmaxf(fmaxf(p_cy + dh1, t_cy + dh2) - fminf(p_cy - dh1, t_cy - dh2), 0.0f);
        float c2v = en_w * en_w + en_h * en_h + MEPS;

        float dx = t_cx - p_cx, dy = t_cy - p_cy;
        float rho2 = dx * dx + dy * dy;

        const float factor = 0.40528473456935108577f;  // 4/pi^2
        float dv = atanf(__fdividef(t_w, t_h + MEPS)) - atanf(__fdividef(p_w, p_h + MEPS));
        float v = factor * dv * dv;
        float alpha = (iou > 0.5f) ? __fdividef(v, 1.0f - iou + v + MEPS) : 0.0f;

        float ciou = iou - (fminf(fmaxf(__fdividef(rho2, c2v), 0.0f), 1.0f) + alpha * v);
        loss += (1.0f - ciou) * weight[i];
    }

    // ---- deterministic fixed-order reduction ----
    #pragma unroll
    for (int o = 16; o > 0; o >>= 1)
        loss += __shfl_down_sync(0xffffffffu, loss, o);
    __shared__ float sm[TPB / 32];
    __shared__ bool isLast;
    if ((tid & 31) == 0) sm[tid >> 5] = loss;
    __syncthreads();
    if (tid < 32) {
        float vsum = (tid < TPB / 32) ? sm[tid] : 0.0f;
        #pragma unroll
        for (int o = TPB / 64; o > 0; o >>= 1)
            vsum += __shfl_down_sync(0xffffffffu, vsum, o);
        if (tid == 0) {
            g_partials[blockIdx.x] = vsum;
            __threadfence();
            int prev = atomicAdd(&g_count, 1);
            isLast = (prev == (int)gridDim.x - 1);
        }
    }
    __syncthreads();
    if (isLast) {
        int nb = gridDim.x;
        float s = 0.0f;
        for (int k = tid; k < nb; k += TPB) s += g_partials[k];
        #pragma unroll
        for (int o = 16; o > 0; o >>= 1)
            s += __shfl_down_sync(0xffffffffu, s, o);
        if ((tid & 31) == 0) sm[tid >> 5] = s;
        __syncthreads();
        if (tid < 32) {
            float vs = (tid < TPB / 32) ? sm[tid] : 0.0f;
            #pragma unroll
            for (int o = TPB / 64; o > 0; o >>= 1)
                vs += __shfl_down_sync(0xffffffffu, vs, o);
            if (tid == 0) {
                out[0] = vs * invN;
                g_count = 0;   // reset for next graph replay
            }
        }
    }
}

extern "C" void kernel_launch(void* const* d_in, const int* in_sizes, int n_in,
                              void* d_out, int out_size) {
    const float* pred   = (const float*)d_in[0];
    const float* target = (const float*)d_in[1];
    const float* weight = (const float*)d_in[2];
    int N = in_sizes[2];  // weight has N elements

    int nb = (N + TPB - 1) / TPB;
    if (nb > RED_MAX) nb = RED_MAX;
    if (nb < 1) nb = 1;

    obb_ciou_kernel<<<nb, TPB>>>(pred, target, weight, (float*)d_out,
                                 N, 1.0f / (float)N);
}

// round 9
// speedup vs baseline: 1.7470x; 1.1950x over previous
#include <cuda_runtime.h>
#include <math.h>

#define NEPS 1e-8f
#define MEPS 1e-6f
#define BTOL 1e-6f
#define MAXV 16
#define RED_MAX 4096
#define TPB 256

__device__ float g_partials[RED_MAX];
__device__ int   g_count = 0;

// Corner order matches reference: x4=[.5,-.5,-.5,.5]*w, y4=[-.5,-.5,.5,.5]*h
__device__ __forceinline__ void box_corners(float cx, float cy, float w, float h,
                                            float c, float s,
                                            float* X, float* Y) {
    float hw = 0.5f * w, hh = 0.5f * h;
    float xs0 =  hw, xs1 = -hw, xs2 = -hw, xs3 =  hw;
    float ys0 = -hh, ys1 = -hh, ys2 =  hh, ys3 =  hh;
    X[0] = xs0 * c - ys0 * s + cx;  Y[0] = xs0 * s + ys0 * c + cy;
    X[1] = xs1 * c - ys1 * s + cx;  Y[1] = xs1 * s + ys1 * c + cy;
    X[2] = xs2 * c - ys2 * s + cx;  Y[2] = xs2 * s + ys2 * c + cy;
    X[3] = xs3 * c - ys3 * s + cx;  Y[3] = xs3 * s + ys3 * c + cy;
}

// Monotone pseudo-angle, order-isomorphic to atan2(y,x) on (-pi, pi].
__device__ __forceinline__ float pseudo_angle(float x, float y) {
    float t = __fdividef(y, fabsf(x) + fabsf(y));
    if (x >= 0.0f) return t;
    return (y >= 0.0f) ? (2.0f - t) : (-2.0f - t);
}

// Order-preserving float -> uint32
__device__ __forceinline__ unsigned int ordered_bits(float f) {
    unsigned int u = __float_as_uint(f);
    return ((int)u < 0) ? ~u : (u | 0x80000000u);
}

// Compare-exchange for the sorting network (branch-free, keys distinct)
#define CE(a, b) { unsigned int lo_ = min(key[a], key[b]); \
                   unsigned int hi_ = max(key[a], key[b]); \
                   key[a] = lo_; key[b] = hi_; }

__global__ __launch_bounds__(TPB, 4)
void obb_ciou_kernel(const float* __restrict__ pred,
                     const float* __restrict__ target,
                     const float* __restrict__ weight,
                     float* __restrict__ out,
                     int N, float invN) {
    __shared__ float2 s_v[MAXV][TPB];   // 32KB; row stride 2048B -> lane-invariant banks
    const int tid = threadIdx.x;
    float2* const col = &s_v[0][tid];   // row k at col[k*TPB]

    float loss = 0.0f;
    for (int i = blockIdx.x * TPB + tid; i < N; i += gridDim.x * TPB) {
        const float* P = pred + (size_t)i * 5;
        const float* T = target + (size_t)i * 5;
        float p_cx = P[0], p_cy = P[1], p_w = P[2], p_h = P[3], p_a = P[4];
        float t_cx = T[0], t_cy = T[1], t_w = T[2], t_h = T[3], t_a = T[4];

        float c1, s1, c2, s2;
        __sincosf(p_a, &s1, &c1);
        __sincosf(t_a, &s2, &c2);

        float X1[4], Y1[4], X2[4], Y2[4];
        box_corners(p_cx, p_cy, p_w, p_h, c1, s1, X1, Y1);
        box_corners(t_cx, t_cy, t_w, t_h, c2, s2, X2, Y2);

        // ---- collect valid vertices (reference concatenation order) ----
        int m = 0;
        float sx = 0.0f, sy = 0.0f;

        // corners1 in box2: a=C2[0], b=C2[1], d=C2[3]   (division-free tests)
        {
            float abx = X2[1] - X2[0], aby = Y2[1] - Y2[0];
            float adx = X2[3] - X2[0], ady = Y2[3] - Y2[0];
            float ab2 = abx * abx + aby * aby;
            float ad2 = adx * adx + ady * ady;
            float ab_lo = -BTOL * ab2, ab_hi = (1.0f + BTOL) * ab2;
            float ad_lo = -BTOL * ad2, ad_hi = (1.0f + BTOL) * ad2;
            #pragma unroll
            for (int k = 0; k < 4; k++) {
                float amx = X1[k] - X2[0], amy = Y1[k] - Y2[0];
                float dab = abx * amx + aby * amy;
                float dad = adx * amx + ady * amy;
                if (dab > ab_lo && dab < ab_hi && dad > ad_lo && dad < ad_hi) {
                    col[m * TPB] = make_float2(X1[k], Y1[k]);
                    sx += X1[k]; sy += Y1[k]; m++;
                }
            }
        }
        // corners2 in box1
        {
            float abx = X1[1] - X1[0], aby = Y1[1] - Y1[0];
            float adx = X1[3] - X1[0], ady = Y1[3] - Y1[0];
            float ab2 = abx * abx + aby * aby;
            float ad2 = adx * adx + ady * ady;
            float ab_lo = -BTOL * ab2, ab_hi = (1.0f + BTOL) * ab2;
            float ad_lo = -BTOL * ad2, ad_hi = (1.0f + BTOL) * ad2;
            #pragma unroll
            for (int k = 0; k < 4; k++) {
                float amx = X2[k] - X1[0], amy = Y2[k] - Y1[0];
                float dab = abx * amx + aby * amy;
                float dad = adx * amx + ady * amy;
                if (dab > ab_lo && dab < ab_hi && dad > ad_lo && dad < ad_hi) {
                    col[m * TPB] = make_float2(X2[k], Y2[k]);
                    sx += X2[k]; sy += Y2[k]; m++;
                }
            }
        }
        // segment intersections, k1-major (matches reshape order)
        #pragma unroll
        for (int k1 = 0; k1 < 4; k1++) {
            float x1 = X1[k1], y1 = Y1[k1];
            float ex = X1[(k1 + 1) & 3] - x1, ey = Y1[(k1 + 1) & 3] - y1;
            #pragma unroll
            for (int k2 = 0; k2 < 4; k2++) {
                float x3 = X2[k2], y3 = Y2[k2];
                float fx = X2[(k2 + 1) & 3] - x3, fy = Y2[(k2 + 1) & 3] - y3;
                float num   = fy * ex - fx * ey;
                float den_t = fx * (y1 - y3) - fy * (x1 - x3);
                float inum  = __fdividef(1.0f, num + NEPS);
                float t = den_t * inum;
                float den_u = ex * (y1 - y3) - ey * (x1 - x3);
                float u = -den_u * inum;
                bool ok = (num != 0.0f) &&
                          (t > 0.0f) && (t < 1.0f) &&
                          (u > 0.0f) && (u < 1.0f);
                if (ok) {
                    float ix = fmaf(t, ex, x1);
                    float iy = fmaf(t, ey, y1);
                    col[m * TPB] = make_float2(ix, iy);
                    sx += ix; sy += iy; m++;
                }
            }
        }

        // ---- order by centroid angle, shoelace ----
        float inter_area = 0.0f;
        if (m > 2 && m <= 8) {
            // fast path: branch-free 8-wide sorting network, keys in registers
            float imf = __fdividef(1.0f, (float)m);
            float ccx = sx * imf, ccy = sy * imf;

            unsigned int key[8];
            #pragma unroll
            for (int slot = 0; slot < 8; slot++) {
                unsigned int kk = 0xFFFFFFFFu;   // sentinel sorts last (real keys < it)
                if (slot < m) {
                    float2 v = col[slot * TPB];
                    unsigned int u = ordered_bits(pseudo_angle(v.x - ccx, v.y - ccy));
                    kk = (u & 0xFFFFFFE0u) | (unsigned int)slot;
                }
                key[slot] = kk;
            }
            // Batcher odd-even merge sort, 8 elements, 19 comparators
            CE(0,1) CE(2,3) CE(4,5) CE(6,7)
            CE(0,2) CE(1,3) CE(4,6) CE(5,7)
            CE(1,2) CE(5,6)
            CE(0,4) CE(1,5) CE(2,6) CE(3,7)
            CE(2,4) CE(3,5)
            CE(1,2) CE(3,4) CE(5,6)

            float2 f0 = col[(int)(key[0] & 0x1Fu) * TPB];
            float px = f0.x, py = f0.y;
            float s = 0.0f;
            #pragma unroll
            for (int r = 1; r < 8; r++) {
                if (r < m) {
                    float2 v = col[(int)(key[r] & 0x1Fu) * TPB];
                    s = fmaf(px, v.y, s);
                    s = fmaf(-py, v.x, s);
                    px = v.x; py = v.y;
                }
            }
            s = fmaf(px, f0.y, s);
            s = fmaf(-py, f0.x, s);
            inter_area = fabsf(s) * 0.5f;
        } else if (m > 8) {
            // rare fallback: insertion sort (tolerance-degenerate cases)
            float imf = __fdividef(1.0f, (float)m);
            float ccx = sx * imf, ccy = sy * imf;

            unsigned int key[MAXV];
            for (int k = 0; k < m; k++) {
                float2 v = col[k * TPB];
                unsigned int u = ordered_bits(pseudo_angle(v.x - ccx, v.y - ccy));
                key[k] = (u & 0xFFFFFFE0u) | (unsigned int)k;
            }
            for (int k = 1; k < m; k++) {
                unsigned int kv = key[k];
                int j = k - 1;
                while (j >= 0 && key[j] > kv) { key[j + 1] = key[j]; j--; }
                key[j + 1] = kv;
            }
            float2 f0 = col[(int)(key[0] & 0x1Fu) * TPB];
            float px = f0.x, py = f0.y;
            float s = 0.0f;
            for (int k = 1; k < m; k++) {
                float2 v = col[(int)(key[k] & 0x1Fu) * TPB];
                s = fmaf(px, v.y, s);
                s = fmaf(-py, v.x, s);
                px = v.x; py = v.y;
            }
            s = fmaf(px, f0.y, s);
            s = fmaf(-py, f0.x, s);
            inter_area = fabsf(s) * 0.5f;
        }

        float area1 = p_w * p_h;
        float area2 = t_w * t_h;
        float iou = __fdividef(inter_area, area1 + area2 - inter_area);
        iou = fminf(fmaxf(iou, 0.0f), 1.0f);

        float ac1 = fabsf(c1), as1 = fabsf(s1);
        float ac2 = fabsf(c2), as2 = fabsf(s2);
        float dw1 = (p_w * ac1 + p_h * as1) * 0.5f;
        float dh1 = (p_w * as1 + p_h * ac1) * 0.5f;
        float dw2 = (t_w * ac2 + t_h * as2) * 0.5f;
        float dh2 = (t_w * as2 + t_h * ac2) * 0.5f;
        float en_w = fmaxf(fmaxf(p_cx + dw1, t_cx + dw2) - fminf(p_cx - dw1, t_cx - dw2), 0.0f);
        float en_h = fmaxf(fmaxf(p_cy + dh1, t_cy + dh2) - fminf(p_cy - dh1, t_cy - dh2), 0.0f);
        float c2v = en_w * en_w + en_h * en_h + MEPS;

        float dx = t_cx - p_cx, dy = t_cy - p_cy;
        float rho2 = dx * dx + dy * dy;

        const float factor = 0.40528473456935108577f;  // 4/pi^2
        float dv = atanf(__fdividef(t_w, t_h + MEPS)) - atanf(__fdividef(p_w, p_h + MEPS));
        float v = factor * dv * dv;
        float alpha = (iou > 0.5f) ? __fdividef(v, 1.0f - iou + v + MEPS) : 0.0f;

        float ciou = iou - (fminf(fmaxf(__fdividef(rho2, c2v), 0.0f), 1.0f) + alpha * v);
        loss += (1.0f - ciou) * weight[i];
    }

    // ---- deterministic fixed-order reduction ----
    #pragma unroll
    for (int o = 16; o > 0; o >>= 1)
        loss += __shfl_down_sync(0xffffffffu, loss, o);
    __shared__ float sm[TPB / 32];
    __shared__ bool isLast;
    if ((tid & 31) == 0) sm[tid >> 5] = loss;
    __syncthreads();
    if (tid < 32) {
        float vsum = (tid < TPB / 32) ? sm[tid] : 0.0f;
        #pragma unroll
        for (int o = TPB / 64; o > 0; o >>= 1)
            vsum += __shfl_down_sync(0xffffffffu, vsum, o);
        if (tid == 0) {
            g_partials[blockIdx.x] = vsum;
            __threadfence();
            int prev = atomicAdd(&g_count, 1);
            isLast = (prev == (int)gridDim.x - 1);
        }
    }
    __syncthreads();
    if (isLast) {
        int nb = gridDim.x;
        float s = 0.0f;
        for (int k = tid; k < nb; k += TPB) s += g_partials[k];
        #pragma unroll
        for (int o = 16; o > 0; o >>= 1)
            s += __shfl_down_sync(0xffffffffu, s, o);
        if ((tid & 31) == 0) sm[tid >> 5] = s;
        __syncthreads();
        if (tid < 32) {
            float vs = (tid < TPB / 32) ? sm[tid] : 0.0f;
            #pragma unroll
            for (int o = TPB / 64; o > 0; o >>= 1)
                vs += __shfl_down_sync(0xffffffffu, vs, o);
            if (tid == 0) {
                out[0] = vs * invN;
                g_count = 0;   // reset for next graph replay
            }
        }
    }
}

extern "C" void kernel_launch(void* const* d_in, const int* in_sizes, int n_in,
                              void* d_out, int out_size) {
    const float* pred   = (const float*)d_in[0];
    const float* target = (const float*)d_in[1];
    const float* weight = (const float*)d_in[2];
    int N = in_sizes[2];  // weight has N elements

    int nb = (N + TPB - 1) / TPB;
    if (nb > RED_MAX) nb = RED_MAX;
    if (nb < 1) nb = 1;

    obb_ciou_kernel<<<nb, TPB>>>(pred, target, weight, (float*)d_out,
                                 N, 1.0f / (float)N);
}

// round 10
// speedup vs baseline: 1.8725x; 1.0718x over previous
#include <cuda_runtime.h>
#include <math.h>

#define NEPS 1e-8f
#define MEPS 1e-6f
#define BTOL 1e-6f
#define MAXV 16
#define RED_MAX 4096
#define TPB 256

__device__ float g_partials[RED_MAX];
__device__ int   g_count = 0;

// Corner order matches reference: x4=[.5,-.5,-.5,.5]*w, y4=[-.5,-.5,.5,.5]*h
__device__ __forceinline__ void box_corners(float cx, float cy, float w, float h,
                                            float c, float s,
                                            float* X, float* Y) {
    float hw = 0.5f * w, hh = 0.5f * h;
    float xs0 =  hw, xs1 = -hw, xs2 = -hw, xs3 =  hw;
    float ys0 = -hh, ys1 = -hh, ys2 =  hh, ys3 =  hh;
    X[0] = xs0 * c - ys0 * s + cx;  Y[0] = xs0 * s + ys0 * c + cy;
    X[1] = xs1 * c - ys1 * s + cx;  Y[1] = xs1 * s + ys1 * c + cy;
    X[2] = xs2 * c - ys2 * s + cx;  Y[2] = xs2 * s + ys2 * c + cy;
    X[3] = xs3 * c - ys3 * s + cx;  Y[3] = xs3 * s + ys3 * c + cy;
}

// Monotone pseudo-angle, order-isomorphic to atan2(y,x) on (-pi, pi].
__device__ __forceinline__ float pseudo_angle(float x, float y) {
    float t = __fdividef(y, fabsf(x) + fabsf(y));
    if (x >= 0.0f) return t;
    return (y >= 0.0f) ? (2.0f - t) : (-2.0f - t);
}

// Order-preserving float -> uint32
__device__ __forceinline__ unsigned int ordered_bits(float f) {
    unsigned int u = __float_as_uint(f);
    return ((int)u < 0) ? ~u : (u | 0x80000000u);
}

// atan for x > 0; A&S 4.4.49 minimax, |err| < 1e-5
__device__ __forceinline__ float fast_atan_pos(float x) {
    bool big = (x > 1.0f);
    float r = big ? __fdividef(1.0f, x) : x;
    float r2 = r * r;
    float p = fmaf(r2, fmaf(r2, fmaf(r2, fmaf(r2, 0.0208351f, -0.0851330f),
                                     0.1801410f), -0.3302995f), 0.9998660f);
    p = r * p;
    return big ? (1.5707963267948966f - p) : p;
}

// Compare-exchange for the sorting network (branch-free, keys distinct)
#define CE(a, b) { unsigned int lo_ = min(key[a], key[b]); \
                   unsigned int hi_ = max(key[a], key[b]); \
                   key[a] = lo_; key[b] = hi_; }

__global__ __launch_bounds__(TPB, 4)
void obb_ciou_kernel(const float* __restrict__ pred,
                     const float* __restrict__ target,
                     const float* __restrict__ weight,
                     float* __restrict__ out,
                     int N, float invN) {
    __shared__ float2 s_v[MAXV][TPB];   // 32KB; row stride 2048B -> lane-invariant banks
    const int tid = threadIdx.x;
    float2* const col = &s_v[0][tid];   // row k at col[k*TPB]

    float loss = 0.0f;
    for (int i = blockIdx.x * TPB + tid; i < N; i += gridDim.x * TPB) {
        const float* P = pred + (size_t)i * 5;
        const float* T = target + (size_t)i * 5;
        float p_cx = P[0], p_cy = P[1], p_w = P[2], p_h = P[3], p_a = P[4];
        float t_cx = T[0], t_cy = T[1], t_w = T[2], t_h = T[3], t_a = T[4];

        float c1, s1, c2, s2;
        __sincosf(p_a, &s1, &c1);
        __sincosf(t_a, &s2, &c2);

        // ---- box1-local frame: box1 axis-aligned, box2 rotated by delta ----
        float hw = 0.5f * p_w, hh = 0.5f * p_h;
        float dxg = t_cx - p_cx, dyg = t_cy - p_cy;
        float rcx =  c1 * dxg + s1 * dyg;          // R1^T * (c2 - c1)
        float rcy =  c1 * dyg - s1 * dxg;
        float cd = c1 * c2 + s1 * s2;              // cos(a2 - a1)
        float sd = c1 * s2 - s1 * c2;              // sin(a2 - a1)

        float X2[4], Y2[4];
        box_corners(rcx, rcy, t_w, t_h, cd, sd, X2, Y2);

        // box1 corners (CW, reference order) in local frame
        const float X1a[4] = { hw, -hw, -hw,  hw };
        const float Y1a[4] = {-hh, -hh,  hh,  hh };
        const float exs[4] = {-p_w, 0.0f, p_w,  0.0f};
        const float eys[4] = { 0.0f, p_h, 0.0f, -p_h};

        // inclusion bounds (== reference p_ab/p_ad in (-tol, 1+tol))
        float bx1 = hw + BTOL * p_w, by1 = hh + BTOL * p_h;
        float bx2 = 0.5f * t_w + BTOL * t_w, by2 = 0.5f * t_h + BTOL * t_h;

        // ---- collect valid vertices (reference concatenation order) ----
        int m = 0;
        float sx = 0.0f, sy = 0.0f;

        // corners1 in box2: rotate into box2 frame, bound check
        #pragma unroll
        for (int k = 0; k < 4; k++) {
            float ux = X1a[k] - rcx, uy = Y1a[k] - rcy;
            float qx = cd * ux + sd * uy;
            float qy = cd * uy - sd * ux;
            if (fabsf(qx) < bx2 && fabsf(qy) < by2) {
                col[m * TPB] = make_float2(X1a[k], Y1a[k]);
                sx += X1a[k]; sy += Y1a[k]; m++;
            }
        }
        // corners2 in box1: direct bound check (box1 axis-aligned)
        #pragma unroll
        for (int k = 0; k < 4; k++) {
            if (fabsf(X2[k]) < bx1 && fabsf(Y2[k]) < by1) {
                col[m * TPB] = make_float2(X2[k], Y2[k]);
                sx += X2[k]; sy += Y2[k]; m++;
            }
        }
        // segment intersections, k1-major (matches reshape order)
        #pragma unroll
        for (int k1 = 0; k1 < 4; k1++) {
            float x1 = X1a[k1], y1 = Y1a[k1];
            float ex = exs[k1],  ey = eys[k1];   // literal zeros fold
            #pragma unroll
            for (int k2 = 0; k2 < 4; k2++) {
                float x3 = X2[k2], y3 = Y2[k2];
                float fx = X2[(k2 + 1) & 3] - x3, fy = Y2[(k2 + 1) & 3] - y3;
                float ax = x1 - x3, ay = y1 - y3;
                float num   = ex * fy - ey * fx;
                float den_t = fx * ay - fy * ax;
                float den_u = ex * ay - ey * ax;
                float inum  = __fdividef(1.0f, num + NEPS);
                float t = den_t * inum;
                float u = -den_u * inum;
                bool ok = (num != 0.0f) &&
                          (t > 0.0f) && (t < 1.0f) &&
                          (u > 0.0f) && (u < 1.0f);
                if (ok) {
                    float ix = fmaf(t, ex, x1);
                    float iy = fmaf(t, ey, y1);
                    col[m * TPB] = make_float2(ix, iy);
                    sx += ix; sy += iy; m++;
                }
            }
        }

        // ---- order by centroid angle, shoelace (area frame-invariant) ----
        float inter_area = 0.0f;
        if (m > 2 && m <= 8) {
            float imf = __fdividef(1.0f, (float)m);
            float ccx = sx * imf, ccy = sy * imf;

            unsigned int key[8];
            #pragma unroll
            for (int slot = 0; slot < 8; slot++) {
                unsigned int kk = 0xFFFFFFFFu;   // sentinel sorts last
                if (slot < m) {
                    float2 v = col[slot * TPB];
                    unsigned int u = ordered_bits(pseudo_angle(v.x - ccx, v.y - ccy));
                    kk = (u & 0xFFFFFFE0u) | (unsigned int)slot;
                }
                key[slot] = kk;
            }
            // Batcher odd-even merge sort, 8 elements, 19 comparators
            CE(0,1) CE(2,3) CE(4,5) CE(6,7)
            CE(0,2) CE(1,3) CE(4,6) CE(5,7)
            CE(1,2) CE(5,6)
            CE(0,4) CE(1,5) CE(2,6) CE(3,7)
            CE(2,4) CE(3,5)
            CE(1,2) CE(3,4) CE(5,6)

            float2 f0 = col[(int)(key[0] & 0x1Fu) * TPB];
            float px = f0.x, py = f0.y;
            float s = 0.0f;
            #pragma unroll
            for (int r = 1; r < 8; r++) {
                if (r < m) {
                    float2 v = col[(int)(key[r] & 0x1Fu) * TPB];
                    s = fmaf(px, v.y, s);
                    s = fmaf(-py, v.x, s);
                    px = v.x; py = v.y;
                }
            }
            s = fmaf(px, f0.y, s);
            s = fmaf(-py, f0.x, s);
            inter_area = fabsf(s) * 0.5f;
        } else if (m > 8) {
            // rare fallback (tolerance-degenerate)
            float imf = __fdividef(1.0f, (float)m);
            float ccx = sx * imf, ccy = sy * imf;

            unsigned int key[MAXV];
            for (int k = 0; k < m; k++) {
                float2 v = col[k * TPB];
                unsigned int u = ordered_bits(pseudo_angle(v.x - ccx, v.y - ccy));
                key[k] = (u & 0xFFFFFFE0u) | (unsigned int)k;
            }
            for (int k = 1; k < m; k++) {
                unsigned int kv = key[k];
                int j = k - 1;
                while (j >= 0 && key[j] > kv) { key[j + 1] = key[j]; j--; }
                key[j + 1] = kv;
            }
            float2 f0 = col[(int)(key[0] & 0x1Fu) * TPB];
            float px = f0.x, py = f0.y;
            float s = 0.0f;
            for (int k = 1; k < m; k++) {
                float2 v = col[(int)(key[k] & 0x1Fu) * TPB];
                s = fmaf(px, v.y, s);
                s = fmaf(-py, v.x, s);
                px = v.x; py = v.y;
            }
            s = fmaf(px, f0.y, s);
            s = fmaf(-py, f0.x, s);
            inter_area = fabsf(s) * 0.5f;
        }

        float area1 = p_w * p_h;
        float area2 = t_w * t_h;
        float iou = __fdividef(inter_area, area1 + area2 - inter_area);
        iou = fminf(fmaxf(iou, 0.0f), 1.0f);

        // horizontal enclosing box (global frame)
        float ac1 = fabsf(c1), as1 = fabsf(s1);
        float ac2 = fabsf(c2), as2 = fabsf(s2);
        float dw1 = (p_w * ac1 + p_h * as1) * 0.5f;
        float dh1 = (p_w * as1 + p_h * ac1) * 0.5f;
        float dw2 = (t_w * ac2 + t_h * as2) * 0.5f;
        float dh2 = (t_w * as2 + t_h * ac2) * 0.5f;
        float en_w = fmaxf(fmaxf(p_cx + dw1, t_cx + dw2) - fminf(p_cx - dw1, t_cx - dw2), 0.0f);
        float en_h = fmaxf(fmaxf(p_cy + dh1, t_cy + dh2) - fminf(p_cy - dh1, t_cy - dh2), 0.0f);
        float c2v = en_w * en_w + en_h * en_h + MEPS;

        float rho2 = dxg * dxg + dyg * dyg;

        const float factor = 0.40528473456935108577f;  // 4/pi^2
        float dv = fast_atan_pos(__fdividef(t_w, t_h + MEPS)) -
                   fast_atan_pos(__fdividef(p_w, p_h + MEPS));
        float v = factor * dv * dv;
        float alpha = (iou > 0.5f) ? __fdividef(v, 1.0f - iou + v + MEPS) : 0.0f;

        float ciou = iou - (fminf(fmaxf(__fdividef(rho2, c2v), 0.0f), 1.0f) + alpha * v);
        loss += (1.0f - ciou) * weight[i];
    }

    // ---- deterministic fixed-order reduction ----
    #pragma unroll
    for (int o = 16; o > 0; o >>= 1)
        loss += __shfl_down_sync(0xffffffffu, loss, o);
    __shared__ float sm[TPB / 32];
    __shared__ bool isLast;
    if ((tid & 31) == 0) sm[tid >> 5] = loss;
    __syncthreads();
    if (tid < 32) {
        float vsum = (tid < TPB / 32) ? sm[tid] : 0.0f;
        #pragma unroll
        for (int o = TPB / 64; o > 0; o >>= 1)
            vsum += __shfl_down_sync(0xffffffffu, vsum, o);
        if (tid == 0) {
            g_partials[blockIdx.x] = vsum;
            __threadfence();
            int prev = atomicAdd(&g_count, 1);
            isLast = (prev == (int)gridDim.x - 1);
        }
    }
    __syncthreads();
    if (isLast) {
        int nb = gridDim.x;
        float s = 0.0f;
        for (int k = tid; k < nb; k += TPB) s += g_partials[k];
        #pragma unroll
        for (int o = 16; o > 0; o >>= 1)
            s += __shfl_down_sync(0xffffffffu, s, o);
        if ((tid & 31) == 0) sm[tid >> 5] = s;
        __syncthreads();
        if (tid < 32) {
            float vs = (tid < TPB / 32) ? sm[tid] : 0.0f;
            #pragma unroll
            for (int o = TPB / 64; o > 0; o >>= 1)
                vs += __shfl_down_sync(0xffffffffu, vs, o);
            if (tid == 0) {
                out[0] = vs * invN;
                g_count = 0;   // reset for next graph replay
            }
        }
    }
}

extern "C" void kernel_launch(void* const* d_in, const int* in_sizes, int n_in,
                              void* d_out, int out_size) {
    const float* pred   = (const float*)d_in[0];
    const float* target = (const float*)d_in[1];
    const float* weight = (const float*)d_in[2];
    int N = in_sizes[2];  // weight has N elements

    int nb = (N + TPB - 1) / TPB;
    if (nb > RED_MAX) nb = RED_MAX;
    if (nb < 1) nb = 1;

    obb_ciou_kernel<<<nb, TPB>>>(pred, target, weight, (float*)d_out,
                                 N, 1.0f / (float)N);
}